// round 2
// baseline (speedup 1.0000x reference)
#include <cuda_runtime.h>
#include <math.h>

#define B 32
#define L 200
#define DIM 36
#define ET 128
#define NH 64

#define OFF_OUT_TE 0
#define OFF_OUT1   (B*ET*DIM)
#define OFF_LOGITS (2*B*ET*DIM)
#define OFF_SXG    (OFF_LOGITS + B*2)
#define OFF_SOUT   (OFF_SXG + B*DIM*DIM)
#define OFF_QP     (OFF_SOUT + B*DIM*DIM)

__device__ float g_qk[ET*ET];
__device__ float g_qkb[ET];
__device__ float g_emb[B*L*ET];
__device__ float g_E[B*ET*L];
__device__ float g_GI[B*ET*192];
__device__ float g_hfin[B*NH];

// ---- key time embeddings: one block per (b,l), 128 threads ----
__global__ void k_emb(const float* __restrict__ ts, const float* __restrict__ pw,
                      const float* __restrict__ pb, const float* __restrict__ tw,
                      const float* __restrict__ tb) {
    int bl = blockIdx.x, j = threadIdx.x;
    float t = ts[bl];
    g_emb[bl*ET + j] = (j == 0) ? fmaf(t, tw[0], tb[0]) : sinf(fmaf(t, pw[j-1], pb[j-1]));
}

// ---- qk[r][j] = sum_d q[r,d]*kw[d,j]; qkb[r] = q[r]·kb; also passthrough qp ----
__global__ void k_qk(const float* __restrict__ qp, const float* __restrict__ pw,
                     const float* __restrict__ pb, const float* __restrict__ tw,
                     const float* __restrict__ tb, const float* __restrict__ qw,
                     const float* __restrict__ qb, const float* __restrict__ kw,
                     const float* __restrict__ kb, float* __restrict__ out) {
    int r = blockIdx.x, j = threadIdx.x;
    __shared__ float e[ET], qr[ET];
    float t = qp[r];
    e[j] = (j == 0) ? fmaf(t, tw[0], tb[0]) : sinf(fmaf(t, pw[j-1], pb[j-1]));
    if (j == 0) out[OFF_QP + r] = t;
    __syncthreads();
    float a = qb[j];
    #pragma unroll 8
    for (int d = 0; d < ET; d++) a = fmaf(qw[j*ET + d], e[d], a);
    qr[j] = a;
    __syncthreads();
    float a2 = 0.f;
    #pragma unroll 8
    for (int d = 0; d < ET; d++) a2 = fmaf(qr[d], kw[d*ET + j], a2);
    g_qk[r*ET + j] = a2;
    if (j == 0) {
        float s = 0.f;
        for (int d = 0; d < ET; d++) s = fmaf(qr[d], kb[d], s);
        g_qkb[r] = s;
    }
}

// ---- E[b,q,l] = exp(score - rowmax); score = (qk[q]·emb[b,l] + qkb[q])/sqrt(ET) ----
__global__ void k_escore() {
    int q0 = blockIdx.x * 32, b = blockIdx.y, tid = threadIdx.x;
    int wy = tid >> 5, lane = tid & 31;
    __shared__ float qks[32*ET];
    __shared__ float ec[224*33];
    for (int i = tid; i < 32*ET; i += 256) qks[i] = g_qk[q0*ET + i];
    float acc[4][7];
    #pragma unroll
    for (int a = 0; a < 4; a++)
        #pragma unroll
        for (int c = 0; c < 7; c++) acc[a][c] = 0.f;
    for (int j0 = 0; j0 < ET; j0 += 32) {
        __syncthreads();
        for (int i = tid; i < 224*32; i += 256) {
            int row = i >> 5, col = i & 31;
            ec[row*33 + col] = (row < L) ? g_emb[(b*L + row)*ET + j0 + col] : 0.f;
        }
        __syncthreads();
        #pragma unroll 4
        for (int j = 0; j < 32; j++) {
            float rq[4];
            #pragma unroll
            for (int qi = 0; qi < 4; qi++) rq[qi] = qks[(wy*4 + qi)*ET + j0 + j];
            #pragma unroll
            for (int li = 0; li < 7; li++) {
                float ev = ec[(lane + 32*li)*33 + j];
                #pragma unroll
                for (int qi = 0; qi < 4; qi++) acc[qi][li] = fmaf(rq[qi], ev, acc[qi][li]);
            }
        }
    }
    const float inv = 0.08838834764831845f;
    #pragma unroll
    for (int qi = 0; qi < 4; qi++) {
        int q = q0 + wy*4 + qi;
        float qkbv = g_qkb[q], s[7], m = -1e30f;
        #pragma unroll
        for (int li = 0; li < 7; li++) {
            int l = lane + 32*li;
            s[li] = (acc[qi][li] + qkbv) * inv;
            if (l < L) m = fmaxf(m, s[li]);
        }
        #pragma unroll
        for (int off = 16; off; off >>= 1) m = fmaxf(m, __shfl_xor_sync(0xffffffffu, m, off));
        #pragma unroll
        for (int li = 0; li < 7; li++) {
            int l = lane + 32*li;
            if (l < L) g_E[(b*ET + q)*L + l] = __expf(s[li] - m);
        }
    }
}

// ---- fused masked-attention GEMM (both masks) + ow epilogue + GRU input gates ----
__global__ void k_mta(const float* __restrict__ x, const int* __restrict__ rm,
                      const float* __restrict__ ow, const float* __restrict__ ob,
                      const float* __restrict__ wih, const float* __restrict__ bih,
                      float* __restrict__ out) {
    int q0 = blockIdx.x * 32, b = blockIdx.y, tid = threadIdx.x;
    int tg = tid >> 5, tc = tid & 31;
    __shared__ float buf[11520];
    float* xs = buf;                 // [32][72]
    float* ys = buf + 2304;          // [32][128] (108 used)
    float* rs = buf + 6400;          // [32]
    float* Es = buf + 6432;          // [32][33]
    float acc[4][4][2];
    #pragma unroll
    for (int a = 0; a < 4; a++)
        #pragma unroll
        for (int c = 0; c < 4; c++) { acc[a][c][0] = 0.f; acc[a][c][1] = 0.f; }
    for (int l0 = 0; l0 < L; l0 += 32) {
        __syncthreads();
        for (int i = tid; i < 32*72; i += 256) {
            int l = i / 72, d = i % 72, gl = l0 + l;
            xs[i] = (gl < L) ? x[(b*L + gl)*72 + d] : 0.f;
        }
        if (tid < 32) {
            int gl = l0 + tid;
            rs[tid] = (gl < L) ? (float)rm[b*L + gl] : 0.f;
        }
        for (int i = tid; i < 32*32; i += 256) {
            int q = i >> 5, l = i & 31, gl = l0 + l;
            Es[q*33 + l] = (gl < L) ? g_E[(b*ET + q0 + q)*L + gl] : 0.f;
        }
        __syncthreads();
        for (int i = tid; i < 32*108; i += 256) {
            int l = i / 108, c = i % 108;
            ys[l*128 + c] = (c < 72) ? xs[l*72 + c] * xs[l*72 + 36 + (c % 36)]
                                     : xs[l*72 + c - 36];
        }
        __syncthreads();
        #pragma unroll 2
        for (int l = 0; l < 32; l++) {
            float rl = rs[l], ev[4], e2[4];
            #pragma unroll
            for (int qi = 0; qi < 4; qi++) {
                ev[qi] = Es[(tg*4 + qi)*33 + l];
                e2[qi] = ev[qi] * rl;
            }
            #pragma unroll
            for (int ci = 0; ci < 4; ci++) {
                if (tc + 32*ci < 108) {
                    float yv = ys[l*128 + tc + 32*ci];
                    #pragma unroll
                    for (int qi = 0; qi < 4; qi++) {
                        acc[qi][ci][0] = fmaf(ev[qi], yv, acc[qi][ci][0]);
                        acc[qi][ci][1] = fmaf(e2[qi], yv, acc[qi][ci][1]);
                    }
                }
            }
        }
    }
    __syncthreads();
    float* Cs = buf;          // [32][216]
    float* os = buf + 6912;   // [32][144]
    #pragma unroll
    for (int ci = 0; ci < 4; ci++) {
        int c = tc + 32*ci;
        if (c < 108) {
            #pragma unroll
            for (int qi = 0; qi < 4; qi++) {
                int q = tg*4 + qi;
                Cs[q*216 + c]       = acc[qi][ci][0];
                Cs[q*216 + 108 + c] = acc[qi][ci][1];
            }
        }
    }
    __syncthreads();
    for (int i = tid; i < 32*144; i += 256) {
        int q = i / 144, c = i % 144, m = c / 72, d = c % 72;
        os[q*144 + c] = Cs[q*216 + m*108 + d] / Cs[q*216 + m*108 + 72 + (d % 36)];
    }
    __syncthreads();
    float* ot = buf;          // [32][36], overlays dead Cs
    for (int i = tid; i < 32*72; i += 256) {
        int q = i / 72, c = i % 72, m = c / 36, dd = c % 36;
        float a = ob[dd];
        #pragma unroll 8
        for (int d = 0; d < 72; d++) a = fmaf(os[q*144 + m*72 + d], ow[dd*72 + d], a);
        out[(m ? OFF_OUT1 : OFF_OUT_TE) + (b*ET + q0 + q)*DIM + dd] = a;
        if (m == 0) ot[q*36 + dd] = a;
    }
    __syncthreads();
    for (int i = tid; i < 32*192; i += 256) {
        int q = i / 192, j = i % 192;
        float a = bih[j];
        #pragma unroll 4
        for (int d = 0; d < 36; d++) a = fmaf(ot[q*36 + d], wih[j*36 + d], a);
        g_GI[(b*ET + q0 + q)*192 + j] = a;
    }
}

// ---- gram matrices: sout (over out_te), sx_g (over x[:,:,:36]) ----
__global__ void k_gram(const float* __restrict__ x, float* __restrict__ out) {
    int b = blockIdx.x, tid = threadIdx.x;   // 144 threads
    __shared__ float ot[ET*36];
    __shared__ float sxs[L*36];
    for (int i = tid; i < ET*36; i += 144) ot[i] = out[OFF_OUT_TE + b*ET*36 + i];
    for (int i = tid; i < L*36; i += 144) sxs[i] = x[(b*L + i/36)*72 + i%36];
    __syncthreads();
    int d0 = (tid / 12) * 3, e0 = (tid % 12) * 3;
    float a[3][3];
    #pragma unroll
    for (int i = 0; i < 3; i++)
        #pragma unroll
        for (int j = 0; j < 3; j++) a[i][j] = 0.f;
    for (int q = 0; q < ET; q++) {
        float u0 = ot[q*36+d0], u1 = ot[q*36+d0+1], u2 = ot[q*36+d0+2];
        float v0 = ot[q*36+e0], v1 = ot[q*36+e0+1], v2 = ot[q*36+e0+2];
        a[0][0]=fmaf(u0,v0,a[0][0]); a[0][1]=fmaf(u0,v1,a[0][1]); a[0][2]=fmaf(u0,v2,a[0][2]);
        a[1][0]=fmaf(u1,v0,a[1][0]); a[1][1]=fmaf(u1,v1,a[1][1]); a[1][2]=fmaf(u1,v2,a[1][2]);
        a[2][0]=fmaf(u2,v0,a[2][0]); a[2][1]=fmaf(u2,v1,a[2][1]); a[2][2]=fmaf(u2,v2,a[2][2]);
    }
    #pragma unroll
    for (int i = 0; i < 3; i++)
        #pragma unroll
        for (int j = 0; j < 3; j++)
            out[OFF_SOUT + b*1296 + (d0+i)*36 + (e0+j)] = 1.f/(1.f + expf(-a[i][j]));
    #pragma unroll
    for (int i = 0; i < 3; i++)
        #pragma unroll
        for (int j = 0; j < 3; j++) a[i][j] = 0.f;
    for (int l = 0; l < L; l++) {
        float u0 = sxs[l*36+d0], u1 = sxs[l*36+d0+1], u2 = sxs[l*36+d0+2];
        float v0 = sxs[l*36+e0], v1 = sxs[l*36+e0+1], v2 = sxs[l*36+e0+2];
        a[0][0]=fmaf(u0,v0,a[0][0]); a[0][1]=fmaf(u0,v1,a[0][1]); a[0][2]=fmaf(u0,v2,a[0][2]);
        a[1][0]=fmaf(u1,v0,a[1][0]); a[1][1]=fmaf(u1,v1,a[1][1]); a[1][2]=fmaf(u1,v2,a[1][2]);
        a[2][0]=fmaf(u2,v0,a[2][0]); a[2][1]=fmaf(u2,v1,a[2][1]); a[2][2]=fmaf(u2,v2,a[2][2]);
    }
    #pragma unroll
    for (int i = 0; i < 3; i++)
        #pragma unroll
        for (int j = 0; j < 3; j++)
            out[OFF_SXG + b*1296 + (d0+i)*36 + (e0+j)] = rintf(1.f/(1.f + expf(-a[i][j])));
}

// ---- GRU scan: one block per batch, 192 threads (one W_hh row each) ----
__global__ void __launch_bounds__(192, 1) k_gru(const float* __restrict__ whh,
                                                const float* __restrict__ bhh_p) {
    int b = blockIdx.x, j = threadIdx.x;
    __shared__ float h[2][64];
    __shared__ float s[192];
    __shared__ float gin[64];
    float w[64];
    #pragma unroll
    for (int i = 0; i < 64; i++) w[i] = whh[j*64 + i];
    float bhh = bhh_p[j];
    if (j < 64) { h[0][j] = 0.f; h[1][j] = 0.f; }
    __syncthreads();
    const float* gi = g_GI + b*ET*192;
    int p = 0;
    for (int t = 0; t < ET; t++) {
        float gij = gi[t*192 + j];
        float a0 = bhh, a1 = 0.f, a2 = 0.f, a3 = 0.f;
        const float4* h4 = (const float4*)h[p];
        #pragma unroll
        for (int i = 0; i < 16; i++) {
            float4 hv = h4[i];
            a0 = fmaf(w[4*i],   hv.x, a0);
            a1 = fmaf(w[4*i+1], hv.y, a1);
            a2 = fmaf(w[4*i+2], hv.z, a2);
            a3 = fmaf(w[4*i+3], hv.w, a3);
        }
        float gh = (a0 + a1) + (a2 + a3);
        if (j < 128) s[j] = gij + gh;
        else { s[j] = gh; gin[j - 128] = gij; }
        __syncthreads();
        if (j < 64) {
            float r = 1.f / (1.f + __expf(-s[j]));
            float z = 1.f / (1.f + __expf(-s[64 + j]));
            float n = tanhf(fmaf(r, s[128 + j], gin[j]));
            h[p ^ 1][j] = n + z * (h[p][j] - n);
        }
        __syncthreads();
        p ^= 1;
    }
    if (j < 64) g_hfin[b*64 + j] = h[p][j];
}

// ---- classifier head: single block ----
__global__ void k_cls(const float* __restrict__ si, const float* __restrict__ stw,
                      const float* __restrict__ stb, const float* __restrict__ c1w,
                      const float* __restrict__ c1b, const float* __restrict__ bng,
                      const float* __restrict__ bnb, const float* __restrict__ c2w,
                      const float* __restrict__ c2b, float* __restrict__ out) {
    __shared__ float ci[32*72];
    __shared__ float zg[32*72];
    int tid = threadIdx.x;  // 256
    for (int i = tid; i < 32*72; i += 256) {
        int b = i / 72, j = i % 72;
        float v;
        if (j < 64) v = g_hfin[b*64 + j];
        else {
            int jj = j - 64;
            float a = stb[jj];
            #pragma unroll
            for (int s = 0; s < 9; s++) a = fmaf(si[b*9 + s], stw[jj*9 + s], a);
            v = a;
        }
        ci[i] = v;
    }
    __syncthreads();
    if (tid < 72) {
        int j = tid;
        float z[32], mu = 0.f, m2 = 0.f;
        for (int b = 0; b < 32; b++) {
            float a = c1b[j];
            #pragma unroll 8
            for (int d = 0; d < 72; d++) a = fmaf(ci[b*72 + d], c1w[j*72 + d], a);
            z[b] = a; mu += a;
        }
        mu *= (1.f / 32.f);
        for (int b = 0; b < 32; b++) { float d = z[b] - mu; m2 = fmaf(d, d, m2); }
        float invs = rsqrtf(m2 * (1.f / 32.f) + 1e-5f);
        float g = bng[j], bb = bnb[j];
        for (int b = 0; b < 32; b++) {
            float zn = (z[b] - mu) * invs * g + bb;
            zg[b*72 + j] = zn * 0.5f * (1.f + erff(zn * 0.7071067811865475f));
        }
    }
    __syncthreads();
    if (tid < 64) {
        int b = tid >> 1, c = tid & 1;
        float a = c2b[c];
        #pragma unroll 8
        for (int d = 0; d < 72; d++) a = fmaf(zg[b*72 + d], c2w[c*72 + d], a);
        out[OFF_LOGITS + b*2 + c] = a;
    }
}

extern "C" void kernel_launch(void* const* d_in, const int* in_sizes, int n_in,
                              void* d_out, int out_size) {
    const float* x    = (const float*)d_in[0];
    const float* ts   = (const float*)d_in[1];
    const float* si   = (const float*)d_in[2];
    const float* qp   = (const float*)d_in[3];
    const float* pw   = (const float*)d_in[4];
    const float* pb   = (const float*)d_in[5];
    const float* tw   = (const float*)d_in[6];
    const float* tb   = (const float*)d_in[7];
    const float* qw   = (const float*)d_in[8];
    const float* qb   = (const float*)d_in[9];
    const float* kw   = (const float*)d_in[10];
    const float* kb   = (const float*)d_in[11];
    const float* ow   = (const float*)d_in[12];
    const float* ob   = (const float*)d_in[13];
    const float* wih  = (const float*)d_in[14];
    const float* whh  = (const float*)d_in[15];
    const float* bih  = (const float*)d_in[16];
    const float* bhh  = (const float*)d_in[17];
    const float* stw  = (const float*)d_in[18];
    const float* stb  = (const float*)d_in[19];
    const float* c1w  = (const float*)d_in[20];
    const float* c1b  = (const float*)d_in[21];
    const float* bng  = (const float*)d_in[22];
    const float* bnb  = (const float*)d_in[23];
    const float* c2w  = (const float*)d_in[24];
    const float* c2b  = (const float*)d_in[25];
    const int*   rm   = (const int*)d_in[26];
    float* out = (float*)d_out;

    k_emb<<<B*L, ET>>>(ts, pw, pb, tw, tb);
    k_qk<<<ET, ET>>>(qp, pw, pb, tw, tb, qw, qb, kw, kb, out);
    k_escore<<<dim3(4, B), 256>>>();
    k_mta<<<dim3(4, B), 256>>>(x, rm, ow, ob, wih, bih, out);
    k_gram<<<B, 144>>>(x, out);
    k_gru<<<B, 192>>>(whh, bhh);
    k_cls<<<1, 256>>>(si, stw, stb, c1w, c1b, bng, bnb, c2w, c2b, out);
}

// round 3
// speedup vs baseline: 1.2163x; 1.2163x over previous
#include <cuda_runtime.h>
#include <math.h>

#define B 32
#define L 200
#define DIM 36
#define ET 128
#define NH 64

#define OFF_OUT_TE 0
#define OFF_OUT1   (B*ET*DIM)
#define OFF_LOGITS (2*B*ET*DIM)
#define OFF_SXG    (OFF_LOGITS + B*2)
#define OFF_SOUT   (OFF_SXG + B*DIM*DIM)
#define OFF_QP     (OFF_SOUT + B*DIM*DIM)

__device__ float g_qk[ET*ET];
__device__ float g_qkb[ET];
__device__ float g_emb[B*L*ET];
__device__ float g_E[B*ET*L];
__device__ float g_GI[B*ET*192];
__device__ float g_hfin[B*NH];

// ---- key time embeddings ----
__global__ void k_emb(const float* __restrict__ ts, const float* __restrict__ pw,
                      const float* __restrict__ pb, const float* __restrict__ tw,
                      const float* __restrict__ tb) {
    int bl = blockIdx.x*2 + (threadIdx.x >> 7);
    int j = threadIdx.x & 127;
    float t = ts[bl];
    g_emb[bl*ET + j] = (j == 0) ? fmaf(t, tw[0], tb[0]) : sinf(fmaf(t, pw[j-1], pb[j-1]));
}

// ---- qk[r][j] = sum_d q[r,d]*kw[d,j]; qkb[r] = q[r]·kb; passthrough qp ----
__global__ void k_qk(const float* __restrict__ qp, const float* __restrict__ pw,
                     const float* __restrict__ pb, const float* __restrict__ tw,
                     const float* __restrict__ tb, const float* __restrict__ qw,
                     const float* __restrict__ qb, const float* __restrict__ kw,
                     const float* __restrict__ kb, float* __restrict__ out) {
    int r = blockIdx.x, j = threadIdx.x;
    __shared__ float e[ET], qr[ET];
    float t = qp[r];
    e[j] = (j == 0) ? fmaf(t, tw[0], tb[0]) : sinf(fmaf(t, pw[j-1], pb[j-1]));
    if (j == 0) out[OFF_QP + r] = t;
    __syncthreads();
    float a = qb[j];
    #pragma unroll 8
    for (int d = 0; d < ET; d++) a = fmaf(qw[j*ET + d], e[d], a);
    qr[j] = a;
    __syncthreads();
    float a2 = 0.f;
    #pragma unroll 8
    for (int d = 0; d < ET; d++) a2 = fmaf(qr[d], kw[d*ET + j], a2);
    g_qk[r*ET + j] = a2;
    if (j == 0) {
        float s = 0.f;
        for (int d = 0; d < ET; d++) s = fmaf(qr[d], kb[d], s);
        g_qkb[r] = s;
    }
}

// ---- E[b,q,l] = exp(score - rowmax). qtile=16, grid dim3(8,B), 256 thr ----
__global__ void __launch_bounds__(256) k_escore() {
    int q0 = blockIdx.x * 16, b = blockIdx.y, tid = threadIdx.x;
    int wy = tid >> 5, lane = tid & 31;
    __shared__ float qks[16*ET];    // 8KB
    __shared__ float ec[224*33];    // 29.5KB
    for (int i = tid; i < 16*ET; i += 256) qks[i] = g_qk[q0*ET + i];
    float acc[2][7];
    #pragma unroll
    for (int a = 0; a < 2; a++)
        #pragma unroll
        for (int c = 0; c < 7; c++) acc[a][c] = 0.f;
    for (int j0 = 0; j0 < ET; j0 += 32) {
        __syncthreads();
        for (int i = tid; i < 224*32; i += 256) {
            int row = i >> 5, col = i & 31;
            ec[row*33 + col] = (row < L) ? g_emb[(b*L + row)*ET + j0 + col] : 0.f;
        }
        __syncthreads();
        #pragma unroll 4
        for (int j = 0; j < 32; j++) {
            float rq0 = qks[(wy*2)*ET + j0 + j];
            float rq1 = qks[(wy*2 + 1)*ET + j0 + j];
            #pragma unroll
            for (int li = 0; li < 7; li++) {
                float ev = ec[(lane + 32*li)*33 + j];
                acc[0][li] = fmaf(rq0, ev, acc[0][li]);
                acc[1][li] = fmaf(rq1, ev, acc[1][li]);
            }
        }
    }
    const float inv = 0.08838834764831845f;
    #pragma unroll
    for (int qi = 0; qi < 2; qi++) {
        int q = q0 + wy*2 + qi;
        float qkbv = g_qkb[q], s[7], m = -1e30f;
        #pragma unroll
        for (int li = 0; li < 7; li++) {
            int l = lane + 32*li;
            s[li] = (acc[qi][li] + qkbv) * inv;
            if (l < L) m = fmaxf(m, s[li]);
        }
        #pragma unroll
        for (int off = 16; off; off >>= 1) m = fmaxf(m, __shfl_xor_sync(0xffffffffu, m, off));
        #pragma unroll
        for (int li = 0; li < 7; li++) {
            int l = lane + 32*li;
            if (l < L) g_E[(b*ET + q)*L + l] = __expf(s[li] - m);
        }
    }
}

// ---- fused masked-attention GEMM (both masks) + ow + GRU input gates ----
// qtile=16, grid dim3(8,B), 256 threads, 27.8KB smem
__global__ void __launch_bounds__(256) k_mta(const float* __restrict__ x, const int* __restrict__ rm,
                      const float* __restrict__ ow, const float* __restrict__ ob,
                      const float* __restrict__ wih, const float* __restrict__ bih,
                      float* __restrict__ out) {
    int q0 = blockIdx.x * 16, b = blockIdx.y, tid = threadIdx.x;
    int tg = tid >> 5, tc = tid & 31;
    __shared__ float buf[6960];
    float* xs = buf;                 // [32][72]   = 2304
    float* ys = buf + 2304;          // [32][128]  = 4096 (108 used, pad zeroed once)
    float* rs = buf + 6400;          // [32]
    float* Es = buf + 6432;          // [16][33]   = 528
    // zero ys pad once
    for (int i = tid; i < 32*20; i += 256) ys[(i/20)*128 + 108 + i%20] = 0.f;
    float acc[2][4][2];
    #pragma unroll
    for (int a = 0; a < 2; a++)
        #pragma unroll
        for (int c = 0; c < 4; c++) { acc[a][c][0] = 0.f; acc[a][c][1] = 0.f; }
    for (int l0 = 0; l0 < L; l0 += 32) {
        __syncthreads();
        for (int i = tid; i < 32*72; i += 256) {
            int l = i / 72, d = i % 72, gl = l0 + l;
            xs[i] = (gl < L) ? x[(b*L + gl)*72 + d] : 0.f;
        }
        if (tid < 32) {
            int gl = l0 + tid;
            rs[tid] = (gl < L) ? (float)rm[b*L + gl] : 0.f;
        }
        for (int i = tid; i < 16*32; i += 256) {
            int q = i >> 5, l = i & 31, gl = l0 + l;
            Es[q*33 + l] = (gl < L) ? g_E[(b*ET + q0 + q)*L + gl] : 0.f;
        }
        __syncthreads();
        for (int i = tid; i < 32*108; i += 256) {
            int l = i / 108, c = i % 108;
            ys[l*128 + c] = (c < 72) ? xs[l*72 + c] * xs[l*72 + 36 + (c % 36)]
                                     : xs[l*72 + c - 36];
        }
        __syncthreads();
        #pragma unroll 4
        for (int l = 0; l < 32; l++) {
            float rl = rs[l];
            float e0 = Es[(tg*2)*33 + l];
            float e1 = Es[(tg*2 + 1)*33 + l];
            float f0 = e0 * rl, f1 = e1 * rl;
            #pragma unroll
            for (int ci = 0; ci < 4; ci++) {
                float yv = ys[l*128 + tc + 32*ci];
                acc[0][ci][0] = fmaf(e0, yv, acc[0][ci][0]);
                acc[0][ci][1] = fmaf(f0, yv, acc[0][ci][1]);
                acc[1][ci][0] = fmaf(e1, yv, acc[1][ci][0]);
                acc[1][ci][1] = fmaf(f1, yv, acc[1][ci][1]);
            }
        }
    }
    __syncthreads();
    float* Cs = buf;          // [16][216] = 3456
    float* os = buf + 3456;   // [16][144] = 2304
    float* ot = buf + 5760;   // [16][36]  = 576
    #pragma unroll
    for (int ci = 0; ci < 4; ci++) {
        int c = tc + 32*ci;
        if (c < 108) {
            #pragma unroll
            for (int qi = 0; qi < 2; qi++) {
                int q = tg*2 + qi;
                Cs[q*216 + c]       = acc[qi][ci][0];
                Cs[q*216 + 108 + c] = acc[qi][ci][1];
            }
        }
    }
    __syncthreads();
    for (int i = tid; i < 16*144; i += 256) {
        int q = i / 144, c = i % 144, m = c / 72, d = c % 72;
        os[q*144 + c] = Cs[q*216 + m*108 + d] / Cs[q*216 + m*108 + 72 + (d % 36)];
    }
    __syncthreads();
    for (int i = tid; i < 16*72; i += 256) {
        int q = i / 72, c = i % 72, m = c / 36, dd = c % 36;
        float a = ob[dd];
        #pragma unroll 8
        for (int d = 0; d < 72; d++) a = fmaf(os[q*144 + m*72 + d], ow[dd*72 + d], a);
        out[(m ? OFF_OUT1 : OFF_OUT_TE) + (b*ET + q0 + q)*DIM + dd] = a;
        if (m == 0) ot[q*36 + dd] = a;
    }
    __syncthreads();
    for (int i = tid; i < 16*192; i += 256) {
        int q = i / 192, j = i % 192;
        float a = bih[j];
        #pragma unroll 4
        for (int d = 0; d < 36; d++) a = fmaf(ot[q*36 + d], wih[j*36 + d], a);
        g_GI[(b*ET + q0 + q)*192 + j] = a;
    }
}

// ---- gram matrices, split: blockIdx.y 0 -> sout(out_te,128), 1 -> sx_g(x,200) ----
__global__ void __launch_bounds__(288) k_gram(const float* __restrict__ x, float* __restrict__ out) {
    int b = blockIdx.x, which = blockIdx.y, tid = threadIdx.x;
    __shared__ float sm[L*36];   // 28.8KB max
    int n = which ? L : ET;
    if (which == 0) {
        for (int i = tid; i < ET*36; i += 288) sm[i] = out[OFF_OUT_TE + b*ET*36 + i];
    } else {
        for (int i = tid; i < L*36; i += 288) sm[i] = x[(b*L + i/36)*72 + i%36];
    }
    __syncthreads();
    int tile = tid % 144, half = tid / 144;
    int d0 = (tile / 12) * 3, e0 = (tile % 12) * 3;
    int i0 = half * (n >> 1), i1 = i0 + (n >> 1);
    float a[3][3];
    #pragma unroll
    for (int i = 0; i < 3; i++)
        #pragma unroll
        for (int j = 0; j < 3; j++) a[i][j] = 0.f;
    for (int r = i0; r < i1; r++) {
        float u0 = sm[r*36+d0], u1 = sm[r*36+d0+1], u2 = sm[r*36+d0+2];
        float v0 = sm[r*36+e0], v1 = sm[r*36+e0+1], v2 = sm[r*36+e0+2];
        a[0][0]=fmaf(u0,v0,a[0][0]); a[0][1]=fmaf(u0,v1,a[0][1]); a[0][2]=fmaf(u0,v2,a[0][2]);
        a[1][0]=fmaf(u1,v0,a[1][0]); a[1][1]=fmaf(u1,v1,a[1][1]); a[1][2]=fmaf(u1,v2,a[1][2]);
        a[2][0]=fmaf(u2,v0,a[2][0]); a[2][1]=fmaf(u2,v1,a[2][1]); a[2][2]=fmaf(u2,v2,a[2][2]);
    }
    __syncthreads();
    float* pr = sm;   // overlay (sm dead)
    if (half == 1) {
        #pragma unroll
        for (int i = 0; i < 3; i++)
            #pragma unroll
            for (int j = 0; j < 3; j++) pr[tile*9 + i*3 + j] = a[i][j];
    }
    __syncthreads();
    if (half == 0) {
        int off = which ? OFF_SXG : OFF_SOUT;
        #pragma unroll
        for (int i = 0; i < 3; i++)
            #pragma unroll
            for (int j = 0; j < 3; j++) {
                float v = a[i][j] + pr[tile*9 + i*3 + j];
                float sg = 1.f / (1.f + expf(-v));
                out[off + b*1296 + (d0+i)*36 + (e0+j)] = which ? rintf(sg) : sg;
            }
    }
}

// ---- GRU scan: one block per batch, 192 threads, gi prefetch ----
__global__ void __launch_bounds__(192, 1) k_gru(const float* __restrict__ whh,
                                                const float* __restrict__ bhh_p) {
    int b = blockIdx.x, j = threadIdx.x;
    __shared__ float h[2][64];
    __shared__ float s[192];
    __shared__ float gin[64];
    float w[64];
    #pragma unroll
    for (int i = 0; i < 64; i++) w[i] = whh[j*64 + i];
    float bhh = bhh_p[j];
    if (j < 64) { h[0][j] = 0.f; h[1][j] = 0.f; }
    const float* gi = g_GI + b*ET*192;
    float gcur = gi[j];
    __syncthreads();
    int p = 0;
    for (int t = 0; t < ET; t++) {
        float gnext = (t < ET-1) ? gi[(t+1)*192 + j] : 0.f;
        float a0 = bhh, a1 = 0.f, a2 = 0.f, a3 = 0.f, a4 = 0.f, a5 = 0.f, a6 = 0.f, a7 = 0.f;
        const float4* h4 = (const float4*)h[p];
        #pragma unroll
        for (int i = 0; i < 8; i++) {
            float4 u = h4[2*i], v = h4[2*i + 1];
            a0 = fmaf(w[8*i],   u.x, a0);
            a1 = fmaf(w[8*i+1], u.y, a1);
            a2 = fmaf(w[8*i+2], u.z, a2);
            a3 = fmaf(w[8*i+3], u.w, a3);
            a4 = fmaf(w[8*i+4], v.x, a4);
            a5 = fmaf(w[8*i+5], v.y, a5);
            a6 = fmaf(w[8*i+6], v.z, a6);
            a7 = fmaf(w[8*i+7], v.w, a7);
        }
        float gh = ((a0 + a1) + (a2 + a3)) + ((a4 + a5) + (a6 + a7));
        if (j < 128) s[j] = gcur + gh;
        else { s[j] = gh; gin[j - 128] = gcur; }
        __syncthreads();
        if (j < 64) {
            float r = __fdividef(1.f, 1.f + __expf(-s[j]));
            float z = __fdividef(1.f, 1.f + __expf(-s[64 + j]));
            float narg = fmaf(r, s[128 + j], gin[j]);
            float e2 = __expf(2.f * narg);
            float n = 1.f - __fdividef(2.f, e2 + 1.f);
            h[p ^ 1][j] = fmaf(z, h[p][j] - n, n);
        }
        __syncthreads();
        gcur = gnext;
        p ^= 1;
    }
    if (j < 64) g_hfin[b*64 + j] = h[p][j];
}

// ---- classifier head: single block, 256 threads ----
__global__ void k_cls(const float* __restrict__ si, const float* __restrict__ stw,
                      const float* __restrict__ stb, const float* __restrict__ c1w,
                      const float* __restrict__ c1b, const float* __restrict__ bng,
                      const float* __restrict__ bnb, const float* __restrict__ c2w,
                      const float* __restrict__ c2b, float* __restrict__ out) {
    __shared__ float ci[32*72];
    __shared__ float zs[32*72];
    __shared__ float mus[72], ivs[72];
    int tid = threadIdx.x;
    for (int i = tid; i < 32*72; i += 256) {
        int b = i / 72, j = i % 72;
        float v;
        if (j < 64) v = g_hfin[b*64 + j];
        else {
            int jj = j - 64;
            float a = stb[jj];
            #pragma unroll
            for (int s = 0; s < 9; s++) a = fmaf(si[b*9 + s], stw[jj*9 + s], a);
            v = a;
        }
        ci[i] = v;
    }
    __syncthreads();
    for (int i = tid; i < 32*72; i += 256) {
        int b = i / 72, j = i % 72;
        float a = c1b[j];
        #pragma unroll 8
        for (int d = 0; d < 72; d++) a = fmaf(ci[b*72 + d], c1w[j*72 + d], a);
        zs[i] = a;
    }
    __syncthreads();
    if (tid < 72) {
        float mu = 0.f;
        for (int b = 0; b < 32; b++) mu += zs[b*72 + tid];
        mu *= (1.f / 32.f);
        float m2 = 0.f;
        for (int b = 0; b < 32; b++) { float d = zs[b*72 + tid] - mu; m2 = fmaf(d, d, m2); }
        mus[tid] = mu;
        ivs[tid] = rsqrtf(m2 * (1.f / 32.f) + 1e-5f);
    }
    __syncthreads();
    for (int i = tid; i < 32*72; i += 256) {
        int j = i % 72;
        float zn = (zs[i] - mus[j]) * ivs[j] * bng[j] + bnb[j];
        zs[i] = zn * 0.5f * (1.f + erff(zn * 0.7071067811865475f));
    }
    __syncthreads();
    if (tid < 64) {
        int b = tid >> 1, c = tid & 1;
        float a = c2b[c];
        #pragma unroll 8
        for (int d = 0; d < 72; d++) a = fmaf(zs[b*72 + d], c2w[c*72 + d], a);
        out[OFF_LOGITS + b*2 + c] = a;
    }
}

extern "C" void kernel_launch(void* const* d_in, const int* in_sizes, int n_in,
                              void* d_out, int out_size) {
    const float* x    = (const float*)d_in[0];
    const float* ts   = (const float*)d_in[1];
    const float* si   = (const float*)d_in[2];
    const float* qp   = (const float*)d_in[3];
    const float* pw   = (const float*)d_in[4];
    const float* pb   = (const float*)d_in[5];
    const float* tw   = (const float*)d_in[6];
    const float* tb   = (const float*)d_in[7];
    const float* qw   = (const float*)d_in[8];
    const float* qb   = (const float*)d_in[9];
    const float* kw   = (const float*)d_in[10];
    const float* kb   = (const float*)d_in[11];
    const float* ow   = (const float*)d_in[12];
    const float* ob   = (const float*)d_in[13];
    const float* wih  = (const float*)d_in[14];
    const float* whh  = (const float*)d_in[15];
    const float* bih  = (const float*)d_in[16];
    const float* bhh  = (const float*)d_in[17];
    const float* stw  = (const float*)d_in[18];
    const float* stb  = (const float*)d_in[19];
    const float* c1w  = (const float*)d_in[20];
    const float* c1b  = (const float*)d_in[21];
    const float* bng  = (const float*)d_in[22];
    const float* bnb  = (const float*)d_in[23];
    const float* c2w  = (const float*)d_in[24];
    const float* c2b  = (const float*)d_in[25];
    const int*   rm   = (const int*)d_in[26];
    float* out = (float*)d_out;

    k_emb<<<B*L/2, 256>>>(ts, pw, pb, tw, tb);
    k_qk<<<ET, ET>>>(qp, pw, pb, tw, tb, qw, qb, kw, kb, out);
    k_escore<<<dim3(8, B), 256>>>();
    k_mta<<<dim3(8, B), 256>>>(x, rm, ow, ob, wih, bih, out);
    k_gram<<<dim3(B, 2), 288>>>(x, out);
    k_gru<<<B, 192>>>(whh, bhh);
    k_cls<<<1, 256>>>(si, stw, stb, c1w, c1b, bng, bnb, c2w, c2b, out);
}